// round 17
// baseline (speedup 1.0000x reference)
#include <cuda_runtime.h>
#include <cuda_fp16.h>
#include <math.h>
#include <stdint.h>

#define B_ 8
#define T_ 1024
#define C_ 2048
#define H_ 16
#define D_ 128
#define C3_ (3*C_)

// Scratch (device globals: allocation-free kernel_launch).
__device__ __half g_qkvh[(size_t)B_*T_*C3_];   // qkv as fp16 (attention input)
__device__ __half g_xh  [(size_t)B_*T_*C_];    // x as fp16
__device__ __half g_wath[(size_t)C_*C3_];      // W_attn^T fp16 [3C][C]
__device__ __half g_wpth[(size_t)C_*C_];       // W_proj^T fp16 [C][C]
__device__ __half g_yh  [(size_t)B_*T_*C_];    // y as fp16

// ===========================================================================
// helpers (base PTX only — ptxas here targets plain sm_103; no tcgen05)
// ===========================================================================
__device__ __forceinline__ uint32_t smem_u32(const void* p) {
    uint32_t a;
    asm("{ .reg .u64 t; cvta.to.shared.u64 t, %1; cvt.u32.u64 %0, t; }"
        : "=r"(a) : "l"(p));
    return a;
}
__device__ __forceinline__ void mma_f16(float* d, const uint32_t* a,
                                        uint32_t b0, uint32_t b1) {
    asm volatile(
        "mma.sync.aligned.m16n8k16.row.col.f32.f16.f16.f32 "
        "{%0,%1,%2,%3}, {%4,%5,%6,%7}, {%8,%9}, {%0,%1,%2,%3};"
        : "+f"(d[0]), "+f"(d[1]), "+f"(d[2]), "+f"(d[3])
        : "r"(a[0]), "r"(a[1]), "r"(a[2]), "r"(a[3]), "r"(b0), "r"(b1));
}
__device__ __forceinline__ void ldsm4(uint32_t* r, uint32_t addr) {
    asm volatile("ldmatrix.sync.aligned.m8n8.x4.shared.b16 {%0,%1,%2,%3}, [%4];"
        : "=r"(r[0]), "=r"(r[1]), "=r"(r[2]), "=r"(r[3]) : "r"(addr));
}
__device__ __forceinline__ void ldsm4t(uint32_t* r, uint32_t addr) {
    asm volatile("ldmatrix.sync.aligned.m8n8.x4.trans.shared.b16 {%0,%1,%2,%3}, [%4];"
        : "=r"(r[0]), "=r"(r[1]), "=r"(r[2]), "=r"(r[3]) : "r"(addr));
}
__device__ __forceinline__ void cp16(uint32_t dst, const void* src) {
    asm volatile("cp.async.cg.shared.global [%0], [%1], 16;"
                 :: "r"(dst), "l"(src));
}
__device__ __forceinline__ void cp_commit() {
    asm volatile("cp.async.commit_group;" ::: "memory");
}
template <int N>
__device__ __forceinline__ void cp_wait() {
    asm volatile("cp.async.wait_group %0;" :: "n"(N) : "memory");
}
__device__ __forceinline__ uint32_t fh2(float a, float b) {
    __half2 h = __floats2half2_rn(a, b);
    return *(uint32_t*)&h;
}

// ===========================================================================
// elementwise fp32 -> fp16
// ===========================================================================
__global__ void cvt_f16_k(const float4* __restrict__ in,
                          __half2* __restrict__ out, int n4)
{
    int i = blockIdx.x * blockDim.x + threadIdx.x;
    if (i < n4) {
        float4 v = in[i];
        out[2*i]   = __floats2half2_rn(v.x, v.y);
        out[2*i+1] = __floats2half2_rn(v.z, v.w);
    }
}

// ===========================================================================
// transpose + convert: in [Kd][Nd] fp32 -> out [Nd][Kd] fp16
// ===========================================================================
__global__ void transpose_cvt_h(const float* __restrict__ in,
                                __half* __restrict__ out, int Kd, int Nd)
{
    __shared__ float tile[32][33];
    const int k0 = blockIdx.y * 32, n0 = blockIdx.x * 32;
    const int tx = threadIdx.x & 31, ty = threadIdx.x >> 5;
#pragma unroll
    for (int p = 0; p < 4; ++p) {
        int k = ty + p * 8;
        tile[k][tx] = in[(size_t)(k0 + k) * Nd + n0 + tx];
    }
    __syncthreads();
#pragma unroll
    for (int p = 0; p < 4; ++p) {
        int n = ty + p * 8;
        out[(size_t)(n0 + n) * Kd + k0 + tx] = __float2half_rn(tile[tx][n]);
    }
}

// ===========================================================================
// fp16 tensor-core GEMM — R14 kernel, VERBATIM (proven 844us config).
// ===========================================================================
#define GEMM_SMEM_CP 98304

template <bool F16OUT>
__global__ __launch_bounds__(256, 2) void gemm_f16(
    const __half* __restrict__ A, const __half* __restrict__ BT,
    const float* __restrict__ bias, void* __restrict__ Cout,
    int M, int N, int K)
{
    extern __shared__ __align__(16) uint32_t sm4[];
    const uint32_t smem_base = smem_u32(sm4);
    const int tid  = threadIdx.x;
    const int lane = tid & 31;
    const int warp = tid >> 5;
    const int wm = warp & 3, wn = warp >> 2;
    const int m0 = blockIdx.y * 128, n0 = blockIdx.x * 128;
    const int NIT = K >> 6;   // BK=64

    float acc[2][8][4];
#pragma unroll
    for (int i = 0; i < 2; ++i)
#pragma unroll
        for (int j = 0; j < 8; ++j)
#pragma unroll
            for (int q = 0; q < 4; ++q) acc[i][j][q] = 0.f;

    auto issue = [&](int kt, int s) {
        const int k0 = kt << 6;
        const uint32_t ab = smem_base + (uint32_t)s * 16384;
#pragma unroll
        for (int p = 0; p < 4; ++p) {
            int i = tid + (p << 8);
            int r = i >> 3, u = i & 7;
            cp16(ab + (uint32_t)(r * 8 + (u ^ (r & 7))) * 16,
                 A + (size_t)(m0 + r) * K + k0 + (u << 3));
        }
        const uint32_t bb = smem_base + 49152u + (uint32_t)s * 16384;
#pragma unroll
        for (int p = 0; p < 4; ++p) {
            int i = tid + (p << 8);
            int r = i >> 3, u = i & 7;
            cp16(bb + (uint32_t)(r * 8 + (u ^ (r & 7))) * 16,
                 BT + (size_t)(n0 + r) * K + k0 + (u << 3));
        }
    };

    const int mlocA = lane & 15;
    const int khA   = lane >> 4;
    const int nlocB = (lane & 7) + ((lane >> 4) << 3);
    const int khB   = (lane >> 3) & 1;

    auto compute = [&](int st) {
        const uint32_t as_b = smem_base + (uint32_t)st * 16384;
        const uint32_t bs_b = smem_base + 49152u + (uint32_t)st * 16384;
        uint32_t af[2][2][4];
        uint32_t bf[3][4];

        auto ldA2 = [&](int ks, int pb) {
#pragma unroll
            for (int i = 0; i < 2; ++i) {
                int row = wm * 32 + i * 16 + mlocA;
                int unit = 2 * ks + khA;
                ldsm4(af[pb][i], as_b + (uint32_t)(row * 8 + (unit ^ (row & 7))) * 16);
            }
        };
        auto ldB1 = [&](int s2, int pb) {
            int ks = s2 >> 2, jj = s2 & 3;
            int row = wn * 64 + jj * 16 + nlocB;
            int unit = 2 * ks + khB;
            ldsm4(bf[pb], bs_b + (uint32_t)(row * 8 + (unit ^ (row & 7))) * 16);
        };

        ldA2(0, 0);
        ldB1(0, 0);
        ldB1(1, 1);
#pragma unroll
        for (int s2 = 0; s2 < 16; ++s2) {
            const int ks = s2 >> 2, jj = s2 & 3;
            if (s2 + 2 < 16) ldB1(s2 + 2, (s2 + 2) % 3);
            if (jj == 2 && ks < 3) ldA2(ks + 1, (ks + 1) & 1);
            const uint32_t* b = bf[s2 % 3];
            uint32_t (*a)[4] = af[ks & 1];
            mma_f16(acc[0][2*jj],   a[0], b[0], b[1]);
            mma_f16(acc[1][2*jj],   a[1], b[0], b[1]);
            mma_f16(acc[0][2*jj+1], a[0], b[2], b[3]);
            mma_f16(acc[1][2*jj+1], a[1], b[2], b[3]);
        }
    };

    issue(0, 0); cp_commit();
    issue(1, 1); cp_commit();
    for (int kt = 0; kt < NIT; ++kt) {
        cp_wait<1>();
        __syncthreads();
        compute(kt % 3);
        if (kt + 2 < NIT) issue(kt + 2, (kt + 2) % 3);
        cp_commit();
    }

#pragma unroll
    for (int i = 0; i < 2; ++i) {
        const int r = m0 + wm * 32 + i * 16 + (lane >> 2);
#pragma unroll
        for (int j = 0; j < 8; ++j) {
            const int c = n0 + wn * 64 + j * 8 + ((lane & 3) << 1);
            float2 bi = *(const float2*)&bias[c];
            float v00 = acc[i][j][0] + bi.x, v01 = acc[i][j][1] + bi.y;
            float v10 = acc[i][j][2] + bi.x, v11 = acc[i][j][3] + bi.y;
            if (F16OUT) {
                __half* Ch = (__half*)Cout;
                *(__half2*)&Ch[(size_t)r * N + c]       = __floats2half2_rn(v00, v01);
                *(__half2*)&Ch[(size_t)(r + 8) * N + c] = __floats2half2_rn(v10, v11);
            } else {
                float* Cc = (float*)Cout;
                *(float2*)&Cc[(size_t)r * N + c]       = make_float2(v00, v01);
                *(float2*)&Cc[(size_t)(r + 8) * N + c] = make_float2(v10, v11);
            }
        }
    }
}

// ===========================================================================
// fp16 tensor-core flash attention (causal), fp32 softmax/accum.
// R15 structure with the Q-ADDRESS FIX: Q row stride in smem is 256 BYTES
// (16 units x 16B); R15 read it as 64 bytes (missing word->byte x4) and
// produced rel_err 0.89. Store and read now both use row*256.
//   - Q persistent in smem (swizzle u^(r&7)); A-frags per-ks via ldsm4.
//   - __launch_bounds__(256, 2); smem 100KB/CTA -> 2 CTAs/SM.
// Smem words: Q 0..8191; K double 8192..16895; V double 16896..25599.
// ===========================================================================
#define AQ_OFF 0
#define AK_OFF 8192
#define AV_OFF 16896
#define ATTN_SMEM 102400

__global__ __launch_bounds__(256, 2) void attn_tc()
{
    extern __shared__ __align__(16) uint32_t smu[];
    const uint32_t smem_base = smem_u32(smu);

    const int tid  = threadIdx.x;
    const int lane = tid & 31;
    const int warp = tid >> 5;
    const int g = lane >> 2;
    const int t = lane & 3;
    const int qt = 7 - (int)blockIdx.x;
    const int b  = blockIdx.y >> 4, h = blockIdx.y & 15;

    const __half* seq = g_qkvh + (size_t)b * T_ * C3_ + h * D_;
    const __half* Qg = seq + (size_t)(qt * 128) * C3_;
    const __half* Kg = seq + C_;
    const __half* Vg = seq + 2 * C_;

    // ---- stage Q into persistent swizzled region (row r: 256B; unit u^(r&7)) ----
#pragma unroll
    for (int p = 0; p < 8; ++p) {
        int i = tid + (p << 8);
        int r = i >> 4, u = i & 15;
        *(uint4*)&smu[AQ_OFF + (r * 16 + (u ^ (r & 7))) * 4] =
            *(const uint4*)(Qg + (size_t)r * C3_ + u * 8);
    }

    float of[16][4];
#pragma unroll
    for (int nf = 0; nf < 16; ++nf)
#pragma unroll
        for (int q = 0; q < 4; ++q) of[nf][q] = 0.f;
    float m0h = -3.0e38f, m1h = -3.0e38f, l0 = 0.f, l1 = 0.f;

    const float scale = 0.08838834764831845f;
    const int rg0 = qt * 128 + warp * 16 + g;
    const int nt  = 2 * qt + 2;

    // ldmatrix lane geometry
    const int mlocA = lane & 15;                         // Q frag row
    const int khA   = lane >> 4;                         // Q frag k-half unit
    const int rowB = (lane & 7) + ((lane >> 4) << 3);    // K x4: +16*jj
    const int colB = ((lane >> 3) & 1) * 8;              // + 16*ks (halves)
    const int rowV = (lane & 7) + (((lane >> 3) & 1) << 3);  // + 16*ks2
    const int colV = (lane >> 4) * 8;                    // + 16*nn (halves)
    // FIXED: row stride is 256 bytes (16 units * 16B), matching the store.
    const uint32_t qrow_base = smem_base +
        (uint32_t)(AQ_OFF * 4 + (warp * 16 + mlocA) * 256);
    const int qswz = (warp * 16 + mlocA) & 7;

    auto issueKV = [&](int kt, int s) {
        const int kv0 = kt * 64;
        const uint32_t kb = smem_base + (uint32_t)(AK_OFF + s * 4352) * 4;
        const uint32_t vb = smem_base + (uint32_t)(AV_OFF + s * 4352) * 4;
#pragma unroll
        for (int p = 0; p < 4; ++p) {
            int i = tid + (p << 8);
            int r = i >> 4, u = i & 15;
            cp16(kb + (uint32_t)(r * 272 + u * 16),
                 Kg + (size_t)(kv0 + r) * C3_ + u * 8);
            cp16(vb + (uint32_t)(r * 272 + u * 16),
                 Vg + (size_t)(kv0 + r) * C3_ + u * 8);
        }
    };

    issueKV(0, 0); cp_commit();
    __syncthreads();   // Q stores visible before any warp's first S-loop ldsm

    for (int kt = 0; kt < nt; ++kt) {
        cp_wait<0>();
        __syncthreads();
        if (kt + 1 < nt) { issueKV(kt + 1, (kt + 1) & 1); cp_commit(); }

        const uint32_t kbase = smem_base + (uint32_t)(AK_OFF + (kt & 1) * 4352) * 4;
        const uint32_t vbase = smem_base + (uint32_t)(AV_OFF + (kt & 1) * 4352) * 4;
        const int kv0 = kt * 64;

        // ---- S = Q K^T : warp 16 x 64, Q frags per-ks from smem ----
        float sc[8][4];
#pragma unroll
        for (int j = 0; j < 8; ++j)
#pragma unroll
            for (int q = 0; q < 4; ++q) sc[j][q] = 0.f;

#pragma unroll
        for (int ks = 0; ks < 8; ++ks) {
            uint32_t qf[4];
            int unit = 2 * ks + khA;
            ldsm4(qf, qrow_base + (uint32_t)((unit ^ qswz) * 16));
#pragma unroll
            for (int jj = 0; jj < 4; ++jj) {
                uint32_t bf[4];
                int row = jj * 16 + rowB;
                int colh = ks * 16 + colB;
                ldsm4(bf, kbase + (uint32_t)(row * 136 + colh) * 2);
                mma_f16(sc[2*jj],   qf, bf[0], bf[1]);
                mma_f16(sc[2*jj+1], qf, bf[2], bf[3]);
            }
        }

        // ---- online softmax (C-frag registers) ----
        {   // half 0
            float mt = -3.0e38f;
#pragma unroll
            for (int j = 0; j < 8; ++j) {
                int cg = kv0 + j * 8 + 2 * t;
                float v0 = sc[j][0] * scale; if (cg > rg0)     v0 = -1.0e9f;
                float v1 = sc[j][1] * scale; if (cg + 1 > rg0) v1 = -1.0e9f;
                sc[j][0] = v0; sc[j][1] = v1;
                mt = fmaxf(mt, fmaxf(v0, v1));
            }
            mt = fmaxf(mt, __shfl_xor_sync(~0u, mt, 1));
            mt = fmaxf(mt, __shfl_xor_sync(~0u, mt, 2));
            float mn = fmaxf(m0h, mt);
            float sum = 0.f;
#pragma unroll
            for (int j = 0; j < 8; ++j) {
                float p0 = __expf(sc[j][0] - mn);
                float p1 = __expf(sc[j][1] - mn);
                sum += p0 + p1;
                sc[j][0] = p0; sc[j][1] = p1;
            }
            sum += __shfl_xor_sync(~0u, sum, 1);
            sum += __shfl_xor_sync(~0u, sum, 2);
            float corr = __expf(m0h - mn);
            l0 = l0 * corr + sum; m0h = mn;
#pragma unroll
            for (int nf = 0; nf < 16; ++nf) { of[nf][0] *= corr; of[nf][1] *= corr; }
        }
        {   // half 1
            float mt = -3.0e38f;
#pragma unroll
            for (int j = 0; j < 8; ++j) {
                int cg = kv0 + j * 8 + 2 * t;
                float v0 = sc[j][2] * scale; if (cg > rg0 + 8)     v0 = -1.0e9f;
                float v1 = sc[j][3] * scale; if (cg + 1 > rg0 + 8) v1 = -1.0e9f;
                sc[j][2] = v0; sc[j][3] = v1;
                mt = fmaxf(mt, fmaxf(v0, v1));
            }
            mt = fmaxf(mt, __shfl_xor_sync(~0u, mt, 1));
            mt = fmaxf(mt, __shfl_xor_sync(~0u, mt, 2));
            float mn = fmaxf(m1h, mt);
            float sum = 0.f;
#pragma unroll
            for (int j = 0; j < 8; ++j) {
                float p0 = __expf(sc[j][2] - mn);
                float p1 = __expf(sc[j][3] - mn);
                sum += p0 + p1;
                sc[j][2] = p0; sc[j][3] = p1;
            }
            sum += __shfl_xor_sync(~0u, sum, 1);
            sum += __shfl_xor_sync(~0u, sum, 2);
            float corr = __expf(m1h - mn);
            l1 = l1 * corr + sum; m1h = mn;
#pragma unroll
            for (int nf = 0; nf < 16; ++nf) { of[nf][2] *= corr; of[nf][3] *= corr; }
        }

        // ---- P: C-frag -> A-frag DIRECT pack ----
        uint32_t pa[4][4];
#pragma unroll
        for (int ks2 = 0; ks2 < 4; ++ks2) {
            pa[ks2][0] = fh2(sc[2*ks2][0],   sc[2*ks2][1]);
            pa[ks2][1] = fh2(sc[2*ks2][2],   sc[2*ks2][3]);
            pa[ks2][2] = fh2(sc[2*ks2+1][0], sc[2*ks2+1][1]);
            pa[ks2][3] = fh2(sc[2*ks2+1][2], sc[2*ks2+1][3]);
        }

        // ---- O += P V : warp 16 x 128, V via ldmatrix.trans ----
#pragma unroll
        for (int ks2 = 0; ks2 < 4; ++ks2) {
#pragma unroll
            for (int nn = 0; nn < 8; ++nn) {
                uint32_t bf[4];
                int row = ks2 * 16 + rowV;
                int cold = nn * 16 + colV;
                ldsm4t(bf, vbase + (uint32_t)(row * 136 + cold) * 2);
                mma_f16(of[2*nn],   pa[ks2], bf[0], bf[1]);
                mma_f16(of[2*nn+1], pa[ks2], bf[2], bf[3]);
            }
        }
    }

    // ---- epilogue: O/l -> g_yh (fp16) with head merge ----
    const float inv0 = 1.0f / l0, inv1 = 1.0f / l1;
    const size_t r0 = (size_t)(b*T_ + qt*128 + warp*16 + g) * C_ + h*D_;
#pragma unroll
    for (int nf = 0; nf < 16; ++nf) {
        const int col = nf * 8 + 2 * t;
        *(__half2*)&g_yh[r0 + col] =
            __floats2half2_rn(of[nf][0] * inv0, of[nf][1] * inv0);
        *(__half2*)&g_yh[r0 + (size_t)8 * C_ + col] =
            __floats2half2_rn(of[nf][2] * inv1, of[nf][3] * inv1);
    }
}

// ---------------------------------------------------------------------------
extern "C" void kernel_launch(void* const* d_in, const int* in_sizes, int n_in,
                              void* d_out, int out_size)
{
    const float* x      = (const float*)d_in[0];
    const float* W_attn = (const float*)d_in[1];
    const float* b_attn = (const float*)d_in[2];
    const float* W_proj = (const float*)d_in[3];
    const float* b_proj = (const float*)d_in[4];
    float* out = (float*)d_out;

    __half *qkvh = nullptr, *xh = nullptr, *wath = nullptr,
           *wpth = nullptr, *yh = nullptr;
    cudaGetSymbolAddress((void**)&qkvh, g_qkvh);
    cudaGetSymbolAddress((void**)&xh,   g_xh);
    cudaGetSymbolAddress((void**)&wath, g_wath);
    cudaGetSymbolAddress((void**)&wpth, g_wpth);
    cudaGetSymbolAddress((void**)&yh,   g_yh);

    cudaFuncSetAttribute(gemm_f16<true>,
                         cudaFuncAttributeMaxDynamicSharedMemorySize, GEMM_SMEM_CP);
    cudaFuncSetAttribute(gemm_f16<false>,
                         cudaFuncAttributeMaxDynamicSharedMemorySize, GEMM_SMEM_CP);
    cudaFuncSetAttribute(attn_tc,
                         cudaFuncAttributeMaxDynamicSharedMemorySize, ATTN_SMEM);

    // 0) one-shot conversions: x -> fp16 row-major, W -> fp16 TRANSPOSED [N][K]
    int n4 = (B_*T_*C_) / 4;
    cvt_f16_k<<<(n4 + 255) / 256, 256>>>((const float4*)x, (__half2*)xh, n4);
    transpose_cvt_h<<<dim3(C3_/32, C_/32), 256>>>(W_attn, wath, C_, C3_);
    transpose_cvt_h<<<dim3(C_/32,  C_/32), 256>>>(W_proj, wpth, C_, C_);

    // 1) qkv = x @ W_attn + b_attn -> fp16        [8192, 6144]
    gemm_f16<true><<<dim3(C3_/128, (B_*T_)/128), 256, GEMM_SMEM_CP>>>(
        xh, wath, b_attn, qkvh, B_*T_, C3_, C_);

    // 2) causal flash attention -> g_yh (fp16)    [8192, 2048]
    attn_tc<<<dim3(T_/128, B_*H_), 256, ATTN_SMEM>>>();

    // 3) out = y @ W_proj + b_proj                [8192, 2048]
    gemm_f16<false><<<dim3(C_/128, (B_*T_)/128), 256, GEMM_SMEM_CP>>>(
        yh, wpth, b_proj, out, B_*T_, C_, C_);
}